// round 3
// baseline (speedup 1.0000x reference)
#include <cuda_runtime.h>
#include <cstdint>

// Problem dims (fixed by the reference)
#define BSZ   2
#define LEN   1024
#define DM    1024
#define DI    2048
#define DS    16
#define DR    64
#define MROWS (BSZ*LEN)     // 2048

// ---------------------------------------------------------------------------
// Scratch (allocation-free: __device__ globals)
// ---------------------------------------------------------------------------
__device__ float g_xz  [MROWS * 2 * DI];   // in_proj output (x | z)
__device__ float g_x   [MROWS * DI];       // conv + silu output
__device__ float g_xdbl[MROWS * 96];       // x_proj output (dt_r | B | C)
__device__ float g_dt  [MROWS * DI];       // softplus(dt)
__device__ float g_y   [MROWS * DI];       // scan output (gated)

__device__ __forceinline__ uint32_t f2tf(float x) {
    uint32_t r;
    asm("cvt.rna.tf32.f32 %0, %1;" : "=r"(r) : "f"(x));
    return r;
}

// ---------------------------------------------------------------------------
// tf32 tensor-core GEMM v2:  C[M,N] (+)= A[M,K-slice] * W[N,K-slice]^T
// Block tile 128x128, 256 threads = 8 warps (2m x 4n), warp tile 64x32.
// Double-buffered smem, register-prefetch of next K stage (16).
// grid.z splits K (ksplit elems per z); atomic=1 -> atomicAdd epilogue.
// act==1: C = softplus(C + bias[n])
// M % 128 == 0, ksplit % 16 == 0 required (true at all call sites).
// ---------------------------------------------------------------------------
__global__ void __launch_bounds__(256, 1) gemm_v2(
    const float* __restrict__ A, int lda,
    const float* __restrict__ W, int ldw,
    float* __restrict__ C, int ldc,
    int N, int ksplit,
    const float* __restrict__ bias, int act, int atomic)
{
    __shared__ uint32_t As[2][128][20];   // pad 20 -> conflict-free frag reads
    __shared__ uint32_t Ws[2][128][20];

    const int bm   = blockIdx.y * 128;
    const int bn   = blockIdx.x * 128;
    const int kb   = blockIdx.z * ksplit;
    const int tid  = threadIdx.x;
    const int warp = tid >> 5;
    const int lane = tid & 31;
    const int wm   = (warp & 1) * 64;
    const int wn   = (warp >> 1) * 32;
    const int g    = lane >> 2;   // group id 0..7
    const int tg   = lane & 3;    // thread-in-group 0..3

    // per-thread load slots: two rows (r0, r0+64), 4 consecutive k at c0
    const int r0 = tid >> 2;          // 0..63
    const int r1 = r0 + 64;
    const int c0 = (tid & 3) * 4;     // 0,4,8,12

    float acc[4][4][4];
#pragma unroll
    for (int i = 0; i < 4; i++)
#pragma unroll
        for (int j = 0; j < 4; j++)
#pragma unroll
            for (int c = 0; c < 4; c++) acc[i][j][c] = 0.f;

    const int nstage = ksplit >> 4;

    float4 pa0, pa1, pw0, pw1;
    const float4 f40 = make_float4(0.f, 0.f, 0.f, 0.f);

    // ---- prologue: load stage 0 into regs, cvt, STS buf 0
    {
        const int k0 = kb;
        pa0 = *(const float4*)&A[(bm + r0) * lda + k0 + c0];
        pa1 = *(const float4*)&A[(bm + r1) * lda + k0 + c0];
        pw0 = (bn + r0 < N) ? *(const float4*)&W[(bn + r0) * ldw + k0 + c0] : f40;
        pw1 = (bn + r1 < N) ? *(const float4*)&W[(bn + r1) * ldw + k0 + c0] : f40;
        uint4 u;
        u.x = f2tf(pa0.x); u.y = f2tf(pa0.y); u.z = f2tf(pa0.z); u.w = f2tf(pa0.w);
        *(uint4*)&As[0][r0][c0] = u;
        u.x = f2tf(pa1.x); u.y = f2tf(pa1.y); u.z = f2tf(pa1.z); u.w = f2tf(pa1.w);
        *(uint4*)&As[0][r1][c0] = u;
        u.x = f2tf(pw0.x); u.y = f2tf(pw0.y); u.z = f2tf(pw0.z); u.w = f2tf(pw0.w);
        *(uint4*)&Ws[0][r0][c0] = u;
        u.x = f2tf(pw1.x); u.y = f2tf(pw1.y); u.z = f2tf(pw1.z); u.w = f2tf(pw1.w);
        *(uint4*)&Ws[0][r1][c0] = u;
    }
    __syncthreads();

    for (int s = 0; s < nstage; s++) {
        const int buf  = s & 1;
        const bool more = (s + 1 < nstage);

        // prefetch next stage from GMEM (overlaps with compute below)
        if (more) {
            const int k0 = kb + (s + 1) * 16;
            pa0 = *(const float4*)&A[(bm + r0) * lda + k0 + c0];
            pa1 = *(const float4*)&A[(bm + r1) * lda + k0 + c0];
            pw0 = (bn + r0 < N) ? *(const float4*)&W[(bn + r0) * ldw + k0 + c0] : f40;
            pw1 = (bn + r1 < N) ? *(const float4*)&W[(bn + r1) * ldw + k0 + c0] : f40;
        }

        // compute stage s
#pragma unroll
        for (int kk = 0; kk < 16; kk += 8) {
            uint32_t af[4][4], bf[4][2];
#pragma unroll
            for (int mf = 0; mf < 4; mf++) {
                const int row = wm + mf * 16 + g;
                af[mf][0] = As[buf][row][kk + tg];
                af[mf][1] = As[buf][row + 8][kk + tg];
                af[mf][2] = As[buf][row][kk + tg + 4];
                af[mf][3] = As[buf][row + 8][kk + tg + 4];
            }
#pragma unroll
            for (int jf = 0; jf < 4; jf++) {
                const int col = wn + jf * 8 + g;
                bf[jf][0] = Ws[buf][col][kk + tg];
                bf[jf][1] = Ws[buf][col][kk + tg + 4];
            }
#pragma unroll
            for (int mf = 0; mf < 4; mf++)
#pragma unroll
                for (int jf = 0; jf < 4; jf++)
                    asm volatile(
                        "mma.sync.aligned.m16n8k8.row.col.f32.tf32.tf32.f32 "
                        "{%0,%1,%2,%3},{%4,%5,%6,%7},{%8,%9},{%0,%1,%2,%3};"
                        : "+f"(acc[mf][jf][0]), "+f"(acc[mf][jf][1]),
                          "+f"(acc[mf][jf][2]), "+f"(acc[mf][jf][3])
                        : "r"(af[mf][0]), "r"(af[mf][1]),
                          "r"(af[mf][2]), "r"(af[mf][3]),
                          "r"(bf[jf][0]), "r"(bf[jf][1]));
        }

        // stage s+1 regs -> smem (other buffer)
        if (more) {
            const int nb = buf ^ 1;
            uint4 u;
            u.x = f2tf(pa0.x); u.y = f2tf(pa0.y); u.z = f2tf(pa0.z); u.w = f2tf(pa0.w);
            *(uint4*)&As[nb][r0][c0] = u;
            u.x = f2tf(pa1.x); u.y = f2tf(pa1.y); u.z = f2tf(pa1.z); u.w = f2tf(pa1.w);
            *(uint4*)&As[nb][r1][c0] = u;
            u.x = f2tf(pw0.x); u.y = f2tf(pw0.y); u.z = f2tf(pw0.z); u.w = f2tf(pw0.w);
            *(uint4*)&Ws[nb][r0][c0] = u;
            u.x = f2tf(pw1.x); u.y = f2tf(pw1.y); u.z = f2tf(pw1.z); u.w = f2tf(pw1.w);
            *(uint4*)&Ws[nb][r1][c0] = u;
        }
        __syncthreads();
    }

    // ---- epilogue
#pragma unroll
    for (int mf = 0; mf < 4; mf++)
#pragma unroll
        for (int jf = 0; jf < 4; jf++) {
            const int nn = bn + wn + jf * 8 + tg * 2;
            if (nn < N) {
                const int m0 = bm + wm + mf * 16 + g;
                float v0 = acc[mf][jf][0], v1 = acc[mf][jf][1];
                float v2 = acc[mf][jf][2], v3 = acc[mf][jf][3];
                if (act) {
                    const float b0 = bias[nn], b1 = bias[nn + 1];
                    v0 += b0; v1 += b1; v2 += b0; v3 += b1;
                    v0 = (v0 > 20.f) ? v0 : log1pf(__expf(v0));
                    v1 = (v1 > 20.f) ? v1 : log1pf(__expf(v1));
                    v2 = (v2 > 20.f) ? v2 : log1pf(__expf(v2));
                    v3 = (v3 > 20.f) ? v3 : log1pf(__expf(v3));
                }
                if (atomic) {
                    atomicAdd(&C[m0 * ldc + nn],       v0);
                    atomicAdd(&C[m0 * ldc + nn + 1],   v1);
                    atomicAdd(&C[(m0 + 8) * ldc + nn],     v2);
                    atomicAdd(&C[(m0 + 8) * ldc + nn + 1], v3);
                } else {
                    float2 p0 = make_float2(v0, v1);
                    float2 p1 = make_float2(v2, v3);
                    *(float2*)&C[m0 * ldc + nn] = p0;
                    *(float2*)&C[(m0 + 8) * ldc + nn] = p1;
                }
            }
        }
}

// ---------------------------------------------------------------------------
__global__ void zero_kernel(float* __restrict__ p, int n)
{
    int i = blockIdx.x * 256 + threadIdx.x;
    if (i < n) p[i] = 0.f;
}

// ---------------------------------------------------------------------------
// Depthwise causal conv (K=4) + bias + SiLU.  Reads x-part of g_xz -> g_x.
// ---------------------------------------------------------------------------
__global__ void conv_silu_kernel(const float* __restrict__ xz,
                                 const float* __restrict__ w,
                                 const float* __restrict__ bias,
                                 float* __restrict__ xout)
{
    int idx = blockIdx.x * blockDim.x + threadIdx.x;   // over MROWS*DI
    int d  = idx & (DI - 1);
    int bl = idx >> 11;                                // (b*L + l)
    int l  = bl & (LEN - 1);
    float accv = bias[d];
#pragma unroll
    for (int k = 0; k < 4; k++) {
        int ll = l + k - 3;
        if (ll >= 0)
            accv += xz[(bl + (ll - l)) * (2 * DI) + d] * w[d * 4 + k];
    }
    xout[idx] = accv / (1.f + __expf(-accv));
}

// ---------------------------------------------------------------------------
// Selective scan + fused gating. Block = 256 threads = 16 d-channels, one b.
// warp: 2 d-channels x 16 states. Chunks of 128 steps staged in smem.
// ---------------------------------------------------------------------------
#define LC 128
__global__ void __launch_bounds__(256) scan_kernel(
    const float* __restrict__ dtp,   // g_dt
    const float* __restrict__ xp,    // g_x
    const float* __restrict__ xdbl,  // g_xdbl (B at col 64, C at col 80)
    const float* __restrict__ A_log,
    const float* __restrict__ Dp,
    const float* __restrict__ xz,    // for z-gate
    float* __restrict__ y)
{
    __shared__ float sB[LC][DS];
    __shared__ float sC[LC][DS];
    __shared__ float sdt[LC][16];
    __shared__ float sx[LC][16];

    const int b   = blockIdx.x / (DI / 16);
    const int d0  = (blockIdx.x % (DI / 16)) * 16;
    const int tid = threadIdx.x;
    const int warp = tid >> 5, lane = tid & 31;
    const int sub = lane >> 4, n = lane & 15;
    const int dl  = warp * 2 + sub;      // 0..15
    const int d   = d0 + dl;

    const float a  = -__expf(A_log[d * DS + n]);
    const float Dv = Dp[d];
    float h = 0.f;

    for (int c = 0; c < LEN / LC; c++) {
        __syncthreads();
        for (int e = tid; e < LC * DS; e += 256) {
            int t = e >> 4, nn = e & 15;
            const float* row = &xdbl[(b * LEN + c * LC + t) * 96];
            sB[t][nn] = row[64 + nn];
            sC[t][nn] = row[80 + nn];
        }
        for (int e = tid; e < LC * 16; e += 256) {
            int t = e >> 4, dd = e & 15;
            int gi = (b * LEN + c * LC + t) * DI + d0 + dd;
            sdt[t][dd] = dtp[gi];
            sx[t][dd]  = xp[gi];
        }
        __syncthreads();

        for (int t = 0; t < LC; t++) {
            float dt = sdt[t][dl];
            float xv = sx[t][dl];
            float dA = __expf(dt * a);
            h = fmaf(dA, h, dt * sB[t][n] * xv);
            float part = h * sC[t][n];
            part += __shfl_xor_sync(0xffffffffu, part, 8);
            part += __shfl_xor_sync(0xffffffffu, part, 4);
            part += __shfl_xor_sync(0xffffffffu, part, 2);
            part += __shfl_xor_sync(0xffffffffu, part, 1);
            if (n == 0) {
                int bl = b * LEN + c * LC + t;
                float z = xz[bl * (2 * DI) + DI + d];
                float gz = z / (1.f + __expf(-z));
                y[bl * DI + d] = (part + xv * Dv) * gz;
            }
        }
    }
}

// ---------------------------------------------------------------------------
extern "C" void kernel_launch(void* const* d_in, const int* in_sizes, int n_in,
                              void* d_out, int out_size)
{
    const float* hidden = (const float*)d_in[0];
    const float* in_w   = (const float*)d_in[1];
    const float* conv_w = (const float*)d_in[2];
    const float* conv_b = (const float*)d_in[3];
    const float* xproj  = (const float*)d_in[4];
    const float* dtw    = (const float*)d_in[5];
    const float* dtb    = (const float*)d_in[6];
    const float* alog   = (const float*)d_in[7];
    const float* Dp     = (const float*)d_in[8];
    const float* outw   = (const float*)d_in[9];
    float* out = (float*)d_out;

    static float *pxz = nullptr, *px = nullptr, *pxd = nullptr,
                 *pdt = nullptr, *py = nullptr;
    if (!pxz) {
        cudaGetSymbolAddress((void**)&pxz, g_xz);
        cudaGetSymbolAddress((void**)&px,  g_x);
        cudaGetSymbolAddress((void**)&pxd, g_xdbl);
        cudaGetSymbolAddress((void**)&pdt, g_dt);
        cudaGetSymbolAddress((void**)&py,  g_y);
    }

    // 1) xz = hidden @ in_proj_w^T          (2048 x 4096 x 1024)
    gemm_v2<<<dim3(2 * DI / 128, MROWS / 128, 1), 256>>>(
        hidden, DM, in_w, DM, pxz, 2 * DI, 2 * DI, DM, nullptr, 0, 0);

    // 2) x = silu(conv1d(x) + b)
    conv_silu_kernel<<<(MROWS * DI) / 256, 256>>>(pxz, conv_w, conv_b, px);

    // 3) x_dbl = x @ x_proj_w^T             (2048 x 96 x 2048), split-K=8
    zero_kernel<<<(MROWS * 96 + 255) / 256, 256>>>(pxd, MROWS * 96);
    gemm_v2<<<dim3(1, MROWS / 128, 8), 256>>>(
        px, DI, xproj, DI, pxd, 96, 96, DI / 8, nullptr, 0, 1);

    // 4) dt = softplus(x_dbl[:, :64] @ dt_proj_w^T + b)   (2048 x 2048 x 64)
    gemm_v2<<<dim3(DI / 128, MROWS / 128, 1), 256>>>(
        pxd, 96, dtw, DR, pdt, DI, DI, DR, dtb, 1, 0);

    // 5) selective scan -> y (includes + x*D and *silu(z))
    scan_kernel<<<BSZ * (DI / 16), 256>>>(pdt, px, pxd, alog, Dp, pxz, py);

    // 6) out = y @ out_proj_w^T             (2048 x 1024 x 2048)
    gemm_v2<<<dim3(DM / 128, MROWS / 128, 1), 256>>>(
        py, DI, outw, DI, out, DM, DM, DI, nullptr, 0, 0);
}

// round 4
// speedup vs baseline: 1.1363x; 1.1363x over previous
#include <cuda_runtime.h>
#include <cstdint>

// Problem dims (fixed by the reference)
#define BSZ   2
#define LEN   1024
#define DM    1024
#define DI    2048
#define DS    16
#define DR    64
#define MROWS (BSZ*LEN)     // 2048

// ---------------------------------------------------------------------------
// Scratch (allocation-free: __device__ globals)
// ---------------------------------------------------------------------------
__device__ float g_xz  [MROWS * 2 * DI];   // in_proj output (x | z)
__device__ float g_x   [MROWS * DI];       // conv + silu output
__device__ float g_xdbl[MROWS * 96];       // x_proj output (dt_r | B | C)
__device__ float g_dt  [MROWS * DI];       // softplus(dt)
__device__ float g_y   [MROWS * DI];       // scan output (gated)

__device__ __forceinline__ uint32_t f2tf(float x) {
    uint32_t r;
    asm("cvt.rna.tf32.f32 %0, %1;" : "=r"(r) : "f"(x));
    return r;
}

__device__ __forceinline__ void cpa16(void* dst, const void* src, int sz) {
    uint32_t d = (uint32_t)__cvta_generic_to_shared(dst);
    asm volatile("cp.async.cg.shared.global [%0], [%1], 16, %2;\n"
                 :: "r"(d), "l"(src), "r"(sz) : "memory");
}

// ---------------------------------------------------------------------------
// tf32 tensor-core GEMM v3:  C[M,N] (+)= A[M,K-slice] * W[N,K-slice]^T
// Block tile 128x128, 256 threads = 8 warps (2m x 4n), warp tile 64x32.
// cp.async double-buffered smem (raw fp32), cvt->tf32 at fragment load.
// grid.z splits K (ksplit per z); atomic=1 -> atomicAdd epilogue.
// act==1: C = softplus(C + bias[n]).
// M % 128 == 0, ksplit % 16 == 0 required (true at all call sites).
// ---------------------------------------------------------------------------
__global__ void __launch_bounds__(256, 2) gemm_v3(
    const float* __restrict__ A, int lda,
    const float* __restrict__ W, int ldw,
    float* __restrict__ C, int ldc,
    int N, int ksplit,
    const float* __restrict__ bias, int act, int atomic)
{
    __shared__ float As[2][128][20];   // pad 20 -> conflict-free frag reads
    __shared__ float Ws[2][128][20];

    const int bm   = blockIdx.y * 128;
    const int bn   = blockIdx.x * 128;
    const int kb   = blockIdx.z * ksplit;
    const int tid  = threadIdx.x;
    const int warp = tid >> 5;
    const int lane = tid & 31;
    const int wm   = (warp & 1) * 64;
    const int wn   = (warp >> 1) * 32;
    const int g    = lane >> 2;   // group id 0..7
    const int tg   = lane & 3;    // thread-in-group 0..3

    // loader mapping: thread handles rows (r0, r0+64), 16B chunk at col c4
    const int r0 = tid >> 2;          // 0..63
    const int c4 = (tid & 3) * 4;     // 0,4,8,12
    const int wsz0 = (bn + r0      < N) ? 16 : 0;
    const int wsz1 = (bn + r0 + 64 < N) ? 16 : 0;
    const float* a0p = &A[(bm + r0)      * lda + kb + c4];
    const float* a1p = &A[(bm + r0 + 64) * lda + kb + c4];
    const float* w0p = &W[(bn + r0)      * ldw + kb + c4];
    const float* w1p = &W[(bn + r0 + 64) * ldw + kb + c4];

    float acc[4][4][4];
#pragma unroll
    for (int i = 0; i < 4; i++)
#pragma unroll
        for (int j = 0; j < 4; j++)
#pragma unroll
            for (int c = 0; c < 4; c++) acc[i][j][c] = 0.f;

    const int nstage = ksplit >> 4;

    // prologue: stage 0
    cpa16(&As[0][r0][c4],      a0p, 16);
    cpa16(&As[0][r0 + 64][c4], a1p, 16);
    cpa16(&Ws[0][r0][c4],      w0p, wsz0);
    cpa16(&Ws[0][r0 + 64][c4], w1p, wsz1);
    asm volatile("cp.async.commit_group;\n" ::: "memory");

    for (int s = 0; s < nstage; s++) {
        const int buf  = s & 1;
        const bool more = (s + 1 < nstage);

        if (more) {
            const int ko = (s + 1) * 16;
            const int nb = buf ^ 1;
            cpa16(&As[nb][r0][c4],      a0p + ko, 16);
            cpa16(&As[nb][r0 + 64][c4], a1p + ko, 16);
            cpa16(&Ws[nb][r0][c4],      w0p + ko, wsz0);
            cpa16(&Ws[nb][r0 + 64][c4], w1p + ko, wsz1);
            asm volatile("cp.async.commit_group;\n" ::: "memory");
            asm volatile("cp.async.wait_group 1;\n" ::: "memory");
        } else {
            asm volatile("cp.async.wait_group 0;\n" ::: "memory");
        }
        __syncthreads();

        const float (*as)[20] = As[buf];
        const float (*ws)[20] = Ws[buf];
#pragma unroll
        for (int kk = 0; kk < 16; kk += 8) {
            uint32_t af[4][4], bf[4][2];
#pragma unroll
            for (int mf = 0; mf < 4; mf++) {
                const int row = wm + mf * 16 + g;
                af[mf][0] = f2tf(as[row][kk + tg]);
                af[mf][1] = f2tf(as[row + 8][kk + tg]);
                af[mf][2] = f2tf(as[row][kk + tg + 4]);
                af[mf][3] = f2tf(as[row + 8][kk + tg + 4]);
            }
#pragma unroll
            for (int jf = 0; jf < 4; jf++) {
                const int col = wn + jf * 8 + g;
                bf[jf][0] = f2tf(ws[col][kk + tg]);
                bf[jf][1] = f2tf(ws[col][kk + tg + 4]);
            }
#pragma unroll
            for (int mf = 0; mf < 4; mf++)
#pragma unroll
                for (int jf = 0; jf < 4; jf++)
                    asm volatile(
                        "mma.sync.aligned.m16n8k8.row.col.f32.tf32.tf32.f32 "
                        "{%0,%1,%2,%3},{%4,%5,%6,%7},{%8,%9},{%0,%1,%2,%3};"
                        : "+f"(acc[mf][jf][0]), "+f"(acc[mf][jf][1]),
                          "+f"(acc[mf][jf][2]), "+f"(acc[mf][jf][3])
                        : "r"(af[mf][0]), "r"(af[mf][1]),
                          "r"(af[mf][2]), "r"(af[mf][3]),
                          "r"(bf[jf][0]), "r"(bf[jf][1]));
        }
        __syncthreads();
    }

    // ---- epilogue
#pragma unroll
    for (int mf = 0; mf < 4; mf++)
#pragma unroll
        for (int jf = 0; jf < 4; jf++) {
            const int nn = bn + wn + jf * 8 + tg * 2;
            if (nn < N) {
                const int m0 = bm + wm + mf * 16 + g;
                float v0 = acc[mf][jf][0], v1 = acc[mf][jf][1];
                float v2 = acc[mf][jf][2], v3 = acc[mf][jf][3];
                if (act) {
                    const float b0 = bias[nn], b1 = bias[nn + 1];
                    v0 += b0; v1 += b1; v2 += b0; v3 += b1;
                    v0 = (v0 > 20.f) ? v0 : log1pf(__expf(v0));
                    v1 = (v1 > 20.f) ? v1 : log1pf(__expf(v1));
                    v2 = (v2 > 20.f) ? v2 : log1pf(__expf(v2));
                    v3 = (v3 > 20.f) ? v3 : log1pf(__expf(v3));
                }
                if (atomic) {
                    atomicAdd(&C[m0 * ldc + nn],           v0);
                    atomicAdd(&C[m0 * ldc + nn + 1],       v1);
                    atomicAdd(&C[(m0 + 8) * ldc + nn],     v2);
                    atomicAdd(&C[(m0 + 8) * ldc + nn + 1], v3);
                } else {
                    *(float2*)&C[m0 * ldc + nn]       = make_float2(v0, v1);
                    *(float2*)&C[(m0 + 8) * ldc + nn] = make_float2(v2, v3);
                }
            }
        }
}

// ---------------------------------------------------------------------------
__global__ void zero_kernel(float* __restrict__ p, int n)
{
    int i = blockIdx.x * 256 + threadIdx.x;
    if (i < n) p[i] = 0.f;
}

// ---------------------------------------------------------------------------
// Depthwise causal conv (K=4) + bias + SiLU.  Reads x-part of g_xz -> g_x.
// ---------------------------------------------------------------------------
__global__ void conv_silu_kernel(const float* __restrict__ xz,
                                 const float* __restrict__ w,
                                 const float* __restrict__ bias,
                                 float* __restrict__ xout)
{
    int idx = blockIdx.x * blockDim.x + threadIdx.x;   // over MROWS*DI
    int d  = idx & (DI - 1);
    int bl = idx >> 11;                                // (b*L + l)
    int l  = bl & (LEN - 1);
    float accv = bias[d];
#pragma unroll
    for (int k = 0; k < 4; k++) {
        int ll = l + k - 3;
        if (ll >= 0)
            accv += xz[(bl + (ll - l)) * (2 * DI) + d] * w[d * 4 + k];
    }
    xout[idx] = accv / (1.f + __expf(-accv));
}

// ---------------------------------------------------------------------------
// Selective scan + fused gating. Block = 256 threads = 16 d-channels, one b.
// warp: 2 d-channels x 16 states. Chunks of 128 steps staged in smem.
// ---------------------------------------------------------------------------
#define LC 128
__global__ void __launch_bounds__(256) scan_kernel(
    const float* __restrict__ dtp,   // g_dt
    const float* __restrict__ xp,    // g_x
    const float* __restrict__ xdbl,  // g_xdbl (B at col 64, C at col 80)
    const float* __restrict__ A_log,
    const float* __restrict__ Dp,
    const float* __restrict__ xz,    // for z-gate
    float* __restrict__ y)
{
    __shared__ float sB[LC][DS];
    __shared__ float sC[LC][DS];
    __shared__ float sdt[LC][16];
    __shared__ float sx[LC][16];

    const int b   = blockIdx.x / (DI / 16);
    const int d0  = (blockIdx.x % (DI / 16)) * 16;
    const int tid = threadIdx.x;
    const int warp = tid >> 5, lane = tid & 31;
    const int sub = lane >> 4, n = lane & 15;
    const int dl  = warp * 2 + sub;      // 0..15
    const int d   = d0 + dl;

    const float a  = -__expf(A_log[d * DS + n]);
    const float Dv = Dp[d];
    float h = 0.f;

    for (int c = 0; c < LEN / LC; c++) {
        __syncthreads();
        for (int e = tid; e < LC * DS; e += 256) {
            int t = e >> 4, nn = e & 15;
            const float* row = &xdbl[(b * LEN + c * LC + t) * 96];
            sB[t][nn] = row[64 + nn];
            sC[t][nn] = row[80 + nn];
        }
        for (int e = tid; e < LC * 16; e += 256) {
            int t = e >> 4, dd = e & 15;
            int gi = (b * LEN + c * LC + t) * DI + d0 + dd;
            sdt[t][dd] = dtp[gi];
            sx[t][dd]  = xp[gi];
        }
        __syncthreads();

        for (int t = 0; t < LC; t++) {
            float dt = sdt[t][dl];
            float xv = sx[t][dl];
            float dA = __expf(dt * a);
            h = fmaf(dA, h, dt * sB[t][n] * xv);
            float part = h * sC[t][n];
            part += __shfl_xor_sync(0xffffffffu, part, 8);
            part += __shfl_xor_sync(0xffffffffu, part, 4);
            part += __shfl_xor_sync(0xffffffffu, part, 2);
            part += __shfl_xor_sync(0xffffffffu, part, 1);
            if (n == 0) {
                int bl = b * LEN + c * LC + t;
                float z = xz[bl * (2 * DI) + DI + d];
                float gz = z / (1.f + __expf(-z));
                y[bl * DI + d] = (part + xv * Dv) * gz;
            }
        }
    }
}

// ---------------------------------------------------------------------------
extern "C" void kernel_launch(void* const* d_in, const int* in_sizes, int n_in,
                              void* d_out, int out_size)
{
    const float* hidden = (const float*)d_in[0];
    const float* in_w   = (const float*)d_in[1];
    const float* conv_w = (const float*)d_in[2];
    const float* conv_b = (const float*)d_in[3];
    const float* xproj  = (const float*)d_in[4];
    const float* dtw    = (const float*)d_in[5];
    const float* dtb    = (const float*)d_in[6];
    const float* alog   = (const float*)d_in[7];
    const float* Dp     = (const float*)d_in[8];
    const float* outw   = (const float*)d_in[9];
    float* out = (float*)d_out;

    static float *pxz = nullptr, *px = nullptr, *pxd = nullptr,
                 *pdt = nullptr, *py = nullptr;
    if (!pxz) {
        cudaGetSymbolAddress((void**)&pxz, g_xz);
        cudaGetSymbolAddress((void**)&px,  g_x);
        cudaGetSymbolAddress((void**)&pxd, g_xdbl);
        cudaGetSymbolAddress((void**)&pdt, g_dt);
        cudaGetSymbolAddress((void**)&py,  g_y);
    }

    // 1) xz = hidden @ in_proj_w^T          (2048 x 4096 x 1024)
    gemm_v3<<<dim3(2 * DI / 128, MROWS / 128, 1), 256>>>(
        hidden, DM, in_w, DM, pxz, 2 * DI, 2 * DI, DM, nullptr, 0, 0);

    // 2) x = silu(conv1d(x) + b)
    conv_silu_kernel<<<(MROWS * DI) / 256, 256>>>(pxz, conv_w, conv_b, px);

    // 3) x_dbl = x @ x_proj_w^T             (2048 x 96 x 2048), split-K=8
    zero_kernel<<<(MROWS * 96 + 255) / 256, 256>>>(pxd, MROWS * 96);
    gemm_v3<<<dim3(1, MROWS / 128, 8), 256>>>(
        px, DI, xproj, DI, pxd, 96, 96, DI / 8, nullptr, 0, 1);

    // 4) dt = softplus(x_dbl[:, :64] @ dt_proj_w^T + b)   (2048 x 2048 x 64)
    gemm_v3<<<dim3(DI / 128, MROWS / 128, 1), 256>>>(
        pxd, 96, dtw, DR, pdt, DI, DI, DR, dtb, 1, 0);

    // 5) selective scan -> y (includes + x*D and *silu(z))
    scan_kernel<<<BSZ * (DI / 16), 256>>>(pdt, px, pxd, alog, Dp, pxz, py);

    // 6) out = y @ out_proj_w^T             (2048 x 1024 x 2048)
    gemm_v3<<<dim3(DM / 128, MROWS / 128, 1), 256>>>(
        py, DI, outw, DI, out, DM, DM, DI, nullptr, 0, 0);
}